// round 6
// baseline (speedup 1.0000x reference)
#include <cuda_runtime.h>
#include <cuda_bf16.h>
#include <math.h>
#include <stdint.h>

// ---------------- problem constants ----------------
#define NN 4096
#define DD 4096
#define OO 4096
#define EE 8
#define RR 16
#define ER 128      // E*R
#define GG 9        // E+1

// ---------------- device scratch (small, proven in R1) ----------------
__device__ float g_gates[NN * GG];      // softmax gates per row (base + 8 experts)
__device__ float g_t[NN * ER];          // gated LoRA intermediate t'[n, e*16+r]
__device__ float g_At[DD * ER];         // lora_A transposed to [d][e*16+r]

// ---------------- f32x2 packed-math helpers (PTX ISA 8.6, sm_100+) ----------------
typedef unsigned long long ull;

__device__ __forceinline__ ull pack2(float x, float y) {
    ull r;
    asm("mov.b64 %0, {%1, %2};" : "=l"(r) : "f"(x), "f"(y));
    return r;
}
__device__ __forceinline__ float2 unpack2(ull v) {
    float2 f;
    asm("mov.b64 {%0, %1}, %2;" : "=f"(f.x), "=f"(f.y) : "l"(v));
    return f;
}
__device__ __forceinline__ void fma2(ull& c, ull a, ull b) {
    asm("fma.rn.f32x2 %0, %1, %2, %0;" : "+l"(c) : "l"(a), "l"(b));
}
__device__ __forceinline__ ull add2(ull a, ull b) {
    ull r;
    asm("add.rn.f32x2 %0, %1, %2;" : "=l"(r) : "l"(a), "l"(b));
    return r;
}
__device__ __forceinline__ ull mul2(ull a, ull b) {
    ull r;
    asm("mul.rn.f32x2 %0, %1, %2;" : "=l"(r) : "l"(a), "l"(b));
    return r;
}

// ---------------- kernel 1: gate logits + top2 + softmax (R1-proven) ----------------
__global__ void gate_kernel(const float* __restrict__ x,
                            const float* __restrict__ gw)
{
    int warp = (blockIdx.x * blockDim.x + threadIdx.x) >> 5;
    int lane = threadIdx.x & 31;
    if (warp >= NN) return;
    const float* xr = x + (size_t)warp * DD;

    float acc[GG];
#pragma unroll
    for (int c = 0; c < GG; c++) acc[c] = 0.f;

    for (int d = lane; d < DD; d += 32) {
        float xv = xr[d];
#pragma unroll
        for (int c = 0; c < GG; c++)
            acc[c] += xv * gw[c * DD + d];
    }
#pragma unroll
    for (int c = 0; c < GG; c++) {
#pragma unroll
        for (int off = 16; off > 0; off >>= 1)
            acc[c] += __shfl_xor_sync(0xFFFFFFFFu, acc[c], off);
    }

    if (lane == 0) {
        float m1 = -INFINITY, m2 = -INFINITY;
        int i1 = -1, i2 = -1;
#pragma unroll
        for (int c = 1; c < GG; c++) {
            float v = acc[c];
            if (v > m1) { m2 = m1; i2 = i1; m1 = v; i1 = c; }
            else if (v > m2) { m2 = v; i2 = c; }
        }
        float vals[GG];
        vals[0] = acc[0];
#pragma unroll
        for (int c = 1; c < GG; c++)
            vals[c] = (c == i1 || c == i2) ? acc[c] : 0.0f;

        float mx = vals[0];
#pragma unroll
        for (int c = 1; c < GG; c++) mx = fmaxf(mx, vals[c]);
        float s = 0.f;
        float e[GG];
#pragma unroll
        for (int c = 0; c < GG; c++) { e[c] = __expf(vals[c] - mx); s += e[c]; }
        float inv = 1.0f / s;
#pragma unroll
        for (int c = 0; c < GG; c++)
            g_gates[warp * GG + c] = e[c] * inv;
    }
}

// ---------------- kernel 2: transpose lora_A -> [d][e*16+r] (R1-proven) ----------------
__global__ void transpose_A_kernel(const float* __restrict__ loraA)
{
    int total = EE * DD * RR;
    for (int i = blockIdx.x * blockDim.x + threadIdx.x; i < total;
         i += gridDim.x * blockDim.x) {
        int e = i / (DD * RR);
        int d = (i / RR) % DD;
        int r = i % RR;
        g_At[d * ER + e * RR + r] = loraA[i];
    }
}

// ---------------- kernel 3: t'[n,c] = gate[n,1+c/16] * (x@At)[n,c] (R1-proven) ----
__global__ void loraA_kernel(const float* __restrict__ x)
{
    __shared__ float xs[16][32];    // transposed x tile
    __shared__ float as[16][ER];    // At tile

    int tid  = threadIdx.x;
    int tcol = tid & 31;            // 32 col-groups of 4
    int trow = tid >> 5;            // 8 row-groups of 4
    int rowBase = blockIdx.x * 32;

    float acc[4][4];
#pragma unroll
    for (int i = 0; i < 4; i++)
#pragma unroll
        for (int j = 0; j < 4; j++) acc[i][j] = 0.f;

    for (int k0 = 0; k0 < DD; k0 += 16) {
#pragma unroll
        for (int j = 0; j < 2; j++) {
            int i = tid * 2 + j;
            int row = i >> 4;
            int kk  = i & 15;
            xs[kk][row] = x[(size_t)(rowBase + row) * DD + k0 + kk];
        }
#pragma unroll
        for (int j = 0; j < 2; j++) {
            int i = tid + j * 256;
            int kk = i >> 5;
            int c4 = i & 31;
            *(float4*)&as[kk][c4 * 4] =
                *(const float4*)&g_At[(size_t)(k0 + kk) * ER + c4 * 4];
        }
        __syncthreads();
#pragma unroll
        for (int kk = 0; kk < 16; kk++) {
            float ra[4], rb[4];
            *(float4*)ra = *(const float4*)&xs[kk][trow * 4];
            *(float4*)rb = *(const float4*)&as[kk][tcol * 4];
#pragma unroll
            for (int i = 0; i < 4; i++)
#pragma unroll
                for (int j = 0; j < 4; j++)
                    acc[i][j] += ra[i] * rb[j];
        }
        __syncthreads();
    }
#pragma unroll
    for (int i = 0; i < 4; i++) {
        int row = rowBase + trow * 4 + i;
#pragma unroll
        for (int j = 0; j < 4; j++) {
            int col = tcol * 4 + j;
            float g = g_gates[row * GG + 1 + (col >> 4)];
            g_t[(size_t)row * ER + col] = g * acc[i][j];
        }
    }
}

// ---------------- kernel 4: main fused GEMM, f32x2 packed math ----------------
// out[n,o] = g0[n]*( x@W + b ) + t' @ B_flat
// Structure identical to R1 (BM=BN=128, BK=8, 256 threads, 8x8/thread);
// inner product uses fma.rn.f32x2 over adjacent-j column pairs.
__global__ void main_gemm_kernel(const float* __restrict__ x,
                                 const float* __restrict__ W,
                                 const float* __restrict__ b,
                                 const float* __restrict__ loraB,
                                 float* __restrict__ out)
{
    __shared__ __align__(16) float As[8][128];   // transposed (k, m)
    __shared__ __align__(16) float Bs[8][128];   // (k, n)

    int tid  = threadIdx.x;
    int tcol = tid & 15;           // 16 col groups of 8
    int trow = tid >> 4;           // 16 row groups of 8
    int rowBase = blockIdx.y * 128;
    int colBase = blockIdx.x * 128;

    // acc2[i][jp] holds columns (2*jp, 2*jp+1) for row i
    ull acc2[8][4];
#pragma unroll
    for (int i = 0; i < 8; i++)
#pragma unroll
        for (int jp = 0; jp < 4; jp++) acc2[i][jp] = 0ull;

    // ----- main K loop over D -----
    {
        int lrow = tid >> 1;           // 0..127
        int lkq  = (tid & 1) * 4;      // 0 or 4
        int bkk  = tid >> 5;           // 0..7
        int bc4  = (tid & 31) * 4;     // 0..124
        for (int d0 = 0; d0 < DD; d0 += 8) {
            float4 xa = *(const float4*)&x[(size_t)(rowBase + lrow) * DD + d0 + lkq];
            As[lkq + 0][lrow] = xa.x;
            As[lkq + 1][lrow] = xa.y;
            As[lkq + 2][lrow] = xa.z;
            As[lkq + 3][lrow] = xa.w;
            *(float4*)&Bs[bkk][bc4] =
                *(const float4*)&W[(size_t)(d0 + bkk) * OO + colBase + bc4];
            __syncthreads();
#pragma unroll
            for (int kk = 0; kk < 8; kk++) {
                float ra[8];
                *(float4*)&ra[0] = *(const float4*)&As[kk][trow * 8];
                *(float4*)&ra[4] = *(const float4*)&As[kk][trow * 8 + 4];
                const ull* bp = (const ull*)&Bs[kk][tcol * 8];
                ull rb0 = bp[0], rb1 = bp[1], rb2 = bp[2], rb3 = bp[3];
#pragma unroll
                for (int i = 0; i < 8; i++) {
                    ull a2 = pack2(ra[i], ra[i]);
                    fma2(acc2[i][0], a2, rb0);
                    fma2(acc2[i][1], a2, rb1);
                    fma2(acc2[i][2], a2, rb2);
                    fma2(acc2[i][3], a2, rb3);
                }
            }
            __syncthreads();
        }
    }

    // ----- apply base gate and bias: acc = g0*(acc + b) -----
    {
#pragma unroll
        for (int i = 0; i < 8; i++) {
            float g0 = g_gates[(rowBase + trow * 8 + i) * GG + 0];
            ull g2 = pack2(g0, g0);
            const ull* bb = (const ull*)&b[colBase + tcol * 8];
#pragma unroll
            for (int jp = 0; jp < 4; jp++)
                acc2[i][jp] = mul2(g2, add2(acc2[i][jp], bb[jp]));
        }
    }

    // ----- LoRA K loop over 128 (t' @ B_flat), accumulate unscaled -----
    {
        int lrow = tid >> 1;
        int lkq  = (tid & 1) * 4;
        int bkk  = tid >> 5;
        int bc4  = (tid & 31) * 4;
        for (int c0 = 0; c0 < ER; c0 += 8) {
            float4 ta = *(const float4*)&g_t[(size_t)(rowBase + lrow) * ER + c0 + lkq];
            As[lkq + 0][lrow] = ta.x;
            As[lkq + 1][lrow] = ta.y;
            As[lkq + 2][lrow] = ta.z;
            As[lkq + 3][lrow] = ta.w;
            *(float4*)&Bs[bkk][bc4] =
                *(const float4*)&loraB[(size_t)(c0 + bkk) * OO + colBase + bc4];
            __syncthreads();
#pragma unroll
            for (int kk = 0; kk < 8; kk++) {
                float ra[8];
                *(float4*)&ra[0] = *(const float4*)&As[kk][trow * 8];
                *(float4*)&ra[4] = *(const float4*)&As[kk][trow * 8 + 4];
                const ull* bp = (const ull*)&Bs[kk][tcol * 8];
                ull rb0 = bp[0], rb1 = bp[1], rb2 = bp[2], rb3 = bp[3];
#pragma unroll
                for (int i = 0; i < 8; i++) {
                    ull a2 = pack2(ra[i], ra[i]);
                    fma2(acc2[i][0], a2, rb0);
                    fma2(acc2[i][1], a2, rb1);
                    fma2(acc2[i][2], a2, rb2);
                    fma2(acc2[i][3], a2, rb3);
                }
            }
            __syncthreads();
        }
    }

    // ----- store -----
#pragma unroll
    for (int i = 0; i < 8; i++) {
        int row = rowBase + trow * 8 + i;
#pragma unroll
        for (int jp = 0; jp < 4; jp += 2) {
            int col = colBase + tcol * 8 + jp * 2;
            float2 v0 = unpack2(acc2[i][jp]);
            float2 v1 = unpack2(acc2[i][jp + 1]);
            float4 v = make_float4(v0.x, v0.y, v1.x, v1.y);
            *(float4*)&out[(size_t)row * OO + col] = v;
        }
    }
}

// ---------------- launcher ----------------
extern "C" void kernel_launch(void* const* d_in, const int* in_sizes, int n_in,
                              void* d_out, int out_size)
{
    const float* x      = (const float*)d_in[0];
    const float* W      = (const float*)d_in[1];
    const float* bias   = (const float*)d_in[2];
    const float* loraA  = (const float*)d_in[3];
    const float* loraB  = (const float*)d_in[4];
    const float* gw     = (const float*)d_in[5];
    // d_in[6] = bvv (unused by the reference computation)
    float* out = (float*)d_out;

    gate_kernel<<<NN / 8, 256>>>(x, gw);
    transpose_A_kernel<<<512, 256>>>(loraA);
    loraA_kernel<<<NN / 32, 256>>>(x);
    main_gemm_kernel<<<dim3(OO / 128, NN / 128), 256>>>(x, W, bias, loraB, out);
}

// round 7
// speedup vs baseline: 1.5913x; 1.5913x over previous
#include <cuda_runtime.h>
#include <cuda_bf16.h>
#include <math.h>
#include <stdint.h>

// ---------------- problem constants ----------------
#define NN 4096
#define DD 4096
#define OO 4096
#define EE 8
#define RR 16
#define ER 128      // E*R
#define GG 9        // E+1

// ---------------- device scratch (small — proven safe footprint) ----------------
__device__ float g_gates[NN * GG];      // softmax gates per row (base + 8 experts)
__device__ float g_t[NN * ER];          // gated LoRA intermediate t'[n, e*16+r]
__device__ float g_At[DD * ER];         // lora_A transposed to [d][e*16+r]

// ---------------- mma.sync helper (sm_80+ baseline ISA) ----------------
__device__ __forceinline__ void mma16816(float* c, const uint32_t* a, const uint32_t* b) {
    asm volatile(
        "mma.sync.aligned.m16n8k16.row.col.f32.bf16.bf16.f32 "
        "{%0,%1,%2,%3}, {%4,%5,%6,%7}, {%8,%9}, {%0,%1,%2,%3};"
        : "+f"(c[0]), "+f"(c[1]), "+f"(c[2]), "+f"(c[3])
        : "r"(a[0]), "r"(a[1]), "r"(a[2]), "r"(a[3]), "r"(b[0]), "r"(b[1]));
}

__device__ __forceinline__ void split_bf16(float v, unsigned short& h, unsigned short& l) {
    __nv_bfloat16 bh = __float2bfloat16(v);
    float r = v - __bfloat162float(bh);
    __nv_bfloat16 bl = __float2bfloat16(r);
    h = __bfloat16_as_ushort(bh);
    l = __bfloat16_as_ushort(bl);
}

// ---------------- kernel 1: gate logits + top2 + softmax (R1-proven) ----------------
__global__ void gate_kernel(const float* __restrict__ x,
                            const float* __restrict__ gw)
{
    int warp = (blockIdx.x * blockDim.x + threadIdx.x) >> 5;
    int lane = threadIdx.x & 31;
    if (warp >= NN) return;
    const float* xr = x + (size_t)warp * DD;

    float acc[GG];
#pragma unroll
    for (int c = 0; c < GG; c++) acc[c] = 0.f;

    for (int d = lane; d < DD; d += 32) {
        float xv = xr[d];
#pragma unroll
        for (int c = 0; c < GG; c++)
            acc[c] += xv * gw[c * DD + d];
    }
#pragma unroll
    for (int c = 0; c < GG; c++) {
#pragma unroll
        for (int off = 16; off > 0; off >>= 1)
            acc[c] += __shfl_xor_sync(0xFFFFFFFFu, acc[c], off);
    }

    if (lane == 0) {
        float m1 = -INFINITY, m2 = -INFINITY;
        int i1 = -1, i2 = -1;
#pragma unroll
        for (int c = 1; c < GG; c++) {
            float v = acc[c];
            if (v > m1) { m2 = m1; i2 = i1; m1 = v; i1 = c; }
            else if (v > m2) { m2 = v; i2 = c; }
        }
        float vals[GG];
        vals[0] = acc[0];
#pragma unroll
        for (int c = 1; c < GG; c++)
            vals[c] = (c == i1 || c == i2) ? acc[c] : 0.0f;

        float mx = vals[0];
#pragma unroll
        for (int c = 1; c < GG; c++) mx = fmaxf(mx, vals[c]);
        float s = 0.f;
        float e[GG];
#pragma unroll
        for (int c = 0; c < GG; c++) { e[c] = __expf(vals[c] - mx); s += e[c]; }
        float inv = 1.0f / s;
#pragma unroll
        for (int c = 0; c < GG; c++)
            g_gates[warp * GG + c] = e[c] * inv;
    }
}

// ---------------- kernel 2: transpose lora_A -> [d][e*16+r] (R1-proven) ----------------
__global__ void transpose_A_kernel(const float* __restrict__ loraA)
{
    int total = EE * DD * RR;
    for (int i = blockIdx.x * blockDim.x + threadIdx.x; i < total;
         i += gridDim.x * blockDim.x) {
        int e = i / (DD * RR);
        int d = (i / RR) % DD;
        int r = i % RR;
        g_At[d * ER + e * RR + r] = loraA[i];
    }
}

// ---------------- kernel 3: t'[n,c] = gate[n,1+c/16] * (x@At)[n,c] (R1-proven) ----
__global__ void loraA_kernel(const float* __restrict__ x)
{
    __shared__ float xs[16][32];
    __shared__ float as[16][ER];

    int tid  = threadIdx.x;
    int tcol = tid & 31;
    int trow = tid >> 5;
    int rowBase = blockIdx.x * 32;

    float acc[4][4];
#pragma unroll
    for (int i = 0; i < 4; i++)
#pragma unroll
        for (int j = 0; j < 4; j++) acc[i][j] = 0.f;

    for (int k0 = 0; k0 < DD; k0 += 16) {
#pragma unroll
        for (int j = 0; j < 2; j++) {
            int i = tid * 2 + j;
            int row = i >> 4;
            int kk  = i & 15;
            xs[kk][row] = x[(size_t)(rowBase + row) * DD + k0 + kk];
        }
#pragma unroll
        for (int j = 0; j < 2; j++) {
            int i = tid + j * 256;
            int kk = i >> 5;
            int c4 = i & 31;
            *(float4*)&as[kk][c4 * 4] =
                *(const float4*)&g_At[(size_t)(k0 + kk) * ER + c4 * 4];
        }
        __syncthreads();
#pragma unroll
        for (int kk = 0; kk < 16; kk++) {
            float ra[4], rb[4];
            *(float4*)ra = *(const float4*)&xs[kk][trow * 4];
            *(float4*)rb = *(const float4*)&as[kk][tcol * 4];
#pragma unroll
            for (int i = 0; i < 4; i++)
#pragma unroll
                for (int j = 0; j < 4; j++)
                    acc[i][j] += ra[i] * rb[j];
        }
        __syncthreads();
    }
#pragma unroll
    for (int i = 0; i < 4; i++) {
        int row = rowBase + trow * 4 + i;
#pragma unroll
        for (int j = 0; j < 4; j++) {
            int col = tcol * 4 + j;
            float g = g_gates[row * GG + 1 + (col >> 4)];
            g_t[(size_t)row * ER + col] = g * acc[i][j];
        }
    }
}

// ---------------- kernel 4: fused tensor-core GEMM with in-kernel bf16 split ----------------
// acc = x@W (128 chunks of K=32), then acc *= g0, then acc += t'@B_flat (4 chunks),
// epilogue: out = acc + g0*bias.
// Split-bf16: per chunk, 3 passes (Ah*Bh + Ah*Bl + Al*Bh), fp32 accumulators.
// BM=BN=128, BK=32, 8 warps (2x4), warp tile 64x32, 256 threads.
#define SA 36    // A smem stride (ushort elements per row)
#define SB 132   // B smem stride (ushort elements per k-row)

__global__ void __launch_bounds__(256) mma_fused_kernel(const float* __restrict__ x,
                                                        const float* __restrict__ W,
                                                        const float* __restrict__ bias,
                                                        const float* __restrict__ loraB,
                                                        float* __restrict__ out)
{
    // A tiles: [m=128][k=32] bf16 hi/lo;  B tiles: [k=32][n=128] bf16 hi/lo
    __shared__ __align__(16) unsigned short Ah[128][SA];
    __shared__ __align__(16) unsigned short Al[128][SA];
    __shared__ __align__(16) unsigned short Bh[32][SB];
    __shared__ __align__(16) unsigned short Bl[32][SB];

    int tid  = threadIdx.x;
    int wid  = tid >> 5;
    int lane = tid & 31;
    int gid  = lane >> 2;   // 0..7
    int tig  = lane & 3;    // 0..3
    int wm = wid >> 2;      // 0..1 (m offset *64)
    int wn = wid & 3;       // 0..3 (n offset *32)
    int rowBase = blockIdx.y * 128;
    int colBase = blockIdx.x * 128;

    float acc[4][4][4];
#pragma unroll
    for (int mi = 0; mi < 4; mi++)
#pragma unroll
        for (int ni = 0; ni < 4; ni++)
#pragma unroll
            for (int q = 0; q < 4; q++) acc[mi][ni][q] = 0.f;

    // thread's tile slots: A: i = tid + it*256 -> row=i>>3, q=i&7  (1024 float4)
    //                      B: i = tid + it*256 -> kr=i>>5,  q=i&31 (1024 float4)
    for (int group = 0; group < 2; group++) {
        const float* Asrc = (group == 0) ? x : g_t;
        const float* Bsrc = (group == 0) ? W : loraB;
        const int Kp      = (group == 0) ? DD : ER;
        const int nchunk  = Kp / 32;

        for (int c = 0; c < nchunk; c++) {
            int k0 = c * 32;
            __syncthreads();   // prior compute finished; safe to overwrite tiles

            // ---- load + convert + store A tile ----
#pragma unroll
            for (int it = 0; it < 4; it++) {
                int i = tid + it * 256;
                int row = i >> 3;
                int q   = i & 7;
                float4 v = *(const float4*)&Asrc[(size_t)(rowBase + row) * Kp + k0 + q * 4];
                unsigned short h0, l0, h1, l1, h2, l2, h3, l3;
                split_bf16(v.x, h0, l0);
                split_bf16(v.y, h1, l1);
                split_bf16(v.z, h2, l2);
                split_bf16(v.w, h3, l3);
                unsigned long long ph = (unsigned long long)h0 | ((unsigned long long)h1 << 16)
                                      | ((unsigned long long)h2 << 32) | ((unsigned long long)h3 << 48);
                unsigned long long pl = (unsigned long long)l0 | ((unsigned long long)l1 << 16)
                                      | ((unsigned long long)l2 << 32) | ((unsigned long long)l3 << 48);
                *(unsigned long long*)&Ah[row][q * 4] = ph;
                *(unsigned long long*)&Al[row][q * 4] = pl;
            }
            // ---- load + convert + store B tile (natural [k][n] layout) ----
#pragma unroll
            for (int it = 0; it < 4; it++) {
                int i = tid + it * 256;
                int kr = i >> 5;
                int q  = i & 31;
                float4 v = *(const float4*)&Bsrc[(size_t)(k0 + kr) * OO + colBase + q * 4];
                unsigned short h0, l0, h1, l1, h2, l2, h3, l3;
                split_bf16(v.x, h0, l0);
                split_bf16(v.y, h1, l1);
                split_bf16(v.z, h2, l2);
                split_bf16(v.w, h3, l3);
                unsigned long long ph = (unsigned long long)h0 | ((unsigned long long)h1 << 16)
                                      | ((unsigned long long)h2 << 32) | ((unsigned long long)h3 << 48);
                unsigned long long pl = (unsigned long long)l0 | ((unsigned long long)l1 << 16)
                                      | ((unsigned long long)l2 << 32) | ((unsigned long long)l3 << 48);
                *(unsigned long long*)&Bh[kr][q * 4] = ph;
                *(unsigned long long*)&Bl[kr][q * 4] = pl;
            }
            __syncthreads();

            // ---- compute: 2 k16 steps x 3 split passes ----
#pragma unroll
            for (int k16 = 0; k16 < 2; k16++) {
                int kb = k16 * 16 + tig * 2;
                // B fragments (assemble from 2x LDS.16; pairs along k)
                uint32_t bh[4][2], bl[4][2];
#pragma unroll
                for (int ni = 0; ni < 4; ni++) {
                    int n = wn * 32 + ni * 8 + gid;
                    bh[ni][0] = (uint32_t)Bh[kb][n]     | ((uint32_t)Bh[kb + 1][n] << 16);
                    bh[ni][1] = (uint32_t)Bh[kb + 8][n] | ((uint32_t)Bh[kb + 9][n] << 16);
                    bl[ni][0] = (uint32_t)Bl[kb][n]     | ((uint32_t)Bl[kb + 1][n] << 16);
                    bl[ni][1] = (uint32_t)Bl[kb + 8][n] | ((uint32_t)Bl[kb + 9][n] << 16);
                }
#pragma unroll
                for (int mi = 0; mi < 4; mi++) {
                    int r = wm * 64 + mi * 16 + gid;
                    // a0: [r][kb], a1: [r+8][kb], a2: [r][kb+8], a3: [r+8][kb+8]
                    uint32_t ah[4], al[4];
                    ah[0] = *(const uint32_t*)&Ah[r][kb];
                    ah[1] = *(const uint32_t*)&Ah[r + 8][kb];
                    ah[2] = *(const uint32_t*)&Ah[r][kb + 8];
                    ah[3] = *(const uint32_t*)&Ah[r + 8][kb + 8];
                    al[0] = *(const uint32_t*)&Al[r][kb];
                    al[1] = *(const uint32_t*)&Al[r + 8][kb];
                    al[2] = *(const uint32_t*)&Al[r][kb + 8];
                    al[3] = *(const uint32_t*)&Al[r + 8][kb + 8];
#pragma unroll
                    for (int ni = 0; ni < 4; ni++) {
                        mma16816(acc[mi][ni], ah, bh[ni]);
                        mma16816(acc[mi][ni], ah, bl[ni]);
                        mma16816(acc[mi][ni], al, bh[ni]);
                    }
                }
            }
        }

        // ---- after base GEMM: scale accumulators by base gate g0 ----
        if (group == 0) {
#pragma unroll
            for (int mi = 0; mi < 4; mi++) {
                int ra = rowBase + wm * 64 + mi * 16 + gid;
                float g0a = g_gates[ra * GG];
                float g0b = g_gates[(ra + 8) * GG];
#pragma unroll
                for (int ni = 0; ni < 4; ni++) {
                    acc[mi][ni][0] *= g0a;
                    acc[mi][ni][1] *= g0a;
                    acc[mi][ni][2] *= g0b;
                    acc[mi][ni][3] *= g0b;
                }
            }
        }
    }

    // ----- epilogue: out = acc + g0 * bias -----
#pragma unroll
    for (int mi = 0; mi < 4; mi++) {
        int ra = rowBase + wm * 64 + mi * 16 + gid;
#pragma unroll
        for (int half = 0; half < 2; half++) {
            int row = ra + half * 8;
            float g0 = g_gates[row * GG];
#pragma unroll
            for (int ni = 0; ni < 4; ni++) {
                int col = colBase + wn * 32 + ni * 8 + tig * 2;
                float2 v;
                v.x = acc[mi][ni][half * 2 + 0] + g0 * bias[col];
                v.y = acc[mi][ni][half * 2 + 1] + g0 * bias[col + 1];
                *(float2*)&out[(size_t)row * OO + col] = v;
            }
        }
    }
}

// ---------------- launcher ----------------
extern "C" void kernel_launch(void* const* d_in, const int* in_sizes, int n_in,
                              void* d_out, int out_size)
{
    const float* x      = (const float*)d_in[0];
    const float* W      = (const float*)d_in[1];
    const float* bias   = (const float*)d_in[2];
    const float* loraA  = (const float*)d_in[3];
    const float* loraB  = (const float*)d_in[4];
    const float* gw     = (const float*)d_in[5];
    // d_in[6] = bvv (unused by the reference computation)
    float* out = (float*)d_out;

    gate_kernel<<<NN / 8, 256>>>(x, gw);
    transpose_A_kernel<<<512, 256>>>(loraA);
    loraA_kernel<<<NN / 32, 256>>>(x);
    mma_fused_kernel<<<dim3(OO / 128, NN / 128), 256>>>(x, W, bias, loraB, out);
}

// round 8
// speedup vs baseline: 2.2940x; 1.4416x over previous
#include <cuda_runtime.h>
#include <cuda_bf16.h>
#include <math.h>
#include <stdint.h>

// ---------------- problem constants ----------------
#define NN 4096
#define DD 4096
#define OO 4096
#define EE 8
#define RR 16
#define ER 128      // E*R
#define GG 9        // E+1

// ---------------- device scratch (small — proven safe footprint) ----------------
__device__ float g_gates[NN * GG];      // softmax gates per row (base + 8 experts)
__device__ float g_t[NN * ER];          // gated LoRA intermediate t'[n, e*16+r]
__device__ float g_At[DD * ER];         // lora_A transposed to [d][e*16+r]

// ---------------- mma.sync helper (sm_80+ baseline ISA) ----------------
__device__ __forceinline__ void mma16816(float* c, const uint32_t* a, const uint32_t* b) {
    asm volatile(
        "mma.sync.aligned.m16n8k16.row.col.f32.bf16.bf16.f32 "
        "{%0,%1,%2,%3}, {%4,%5,%6,%7}, {%8,%9}, {%0,%1,%2,%3};"
        : "+f"(c[0]), "+f"(c[1]), "+f"(c[2]), "+f"(c[3])
        : "r"(a[0]), "r"(a[1]), "r"(a[2]), "r"(a[3]), "r"(b[0]), "r"(b[1]));
}

// packed split: (v0,v1) -> h01 (bf16x2 hi parts), l01 (bf16x2 lo residuals)
__device__ __forceinline__ void split2(float v0, float v1, uint32_t& h01, uint32_t& l01) {
    asm("cvt.rn.bf16x2.f32 %0, %1, %2;" : "=r"(h01) : "f"(v1), "f"(v0));
    float f0 = __uint_as_float(h01 << 16);            // bf16 -> f32 is exact <<16
    float f1 = __uint_as_float(h01 & 0xffff0000u);
    float r0 = v0 - f0;
    float r1 = v1 - f1;
    asm("cvt.rn.bf16x2.f32 %0, %1, %2;" : "=r"(l01) : "f"(r1), "f"(r0));
}

// ---------------- kernel 1: gate logits + top2 + softmax (R1-proven) ----------------
__global__ void gate_kernel(const float* __restrict__ x,
                            const float* __restrict__ gw)
{
    int warp = (blockIdx.x * blockDim.x + threadIdx.x) >> 5;
    int lane = threadIdx.x & 31;
    if (warp >= NN) return;
    const float* xr = x + (size_t)warp * DD;

    float acc[GG];
#pragma unroll
    for (int c = 0; c < GG; c++) acc[c] = 0.f;

    for (int d = lane; d < DD; d += 32) {
        float xv = xr[d];
#pragma unroll
        for (int c = 0; c < GG; c++)
            acc[c] += xv * gw[c * DD + d];
    }
#pragma unroll
    for (int c = 0; c < GG; c++) {
#pragma unroll
        for (int off = 16; off > 0; off >>= 1)
            acc[c] += __shfl_xor_sync(0xFFFFFFFFu, acc[c], off);
    }

    if (lane == 0) {
        float m1 = -INFINITY, m2 = -INFINITY;
        int i1 = -1, i2 = -1;
#pragma unroll
        for (int c = 1; c < GG; c++) {
            float v = acc[c];
            if (v > m1) { m2 = m1; i2 = i1; m1 = v; i1 = c; }
            else if (v > m2) { m2 = v; i2 = c; }
        }
        float vals[GG];
        vals[0] = acc[0];
#pragma unroll
        for (int c = 1; c < GG; c++)
            vals[c] = (c == i1 || c == i2) ? acc[c] : 0.0f;

        float mx = vals[0];
#pragma unroll
        for (int c = 1; c < GG; c++) mx = fmaxf(mx, vals[c]);
        float s = 0.f;
        float e[GG];
#pragma unroll
        for (int c = 0; c < GG; c++) { e[c] = __expf(vals[c] - mx); s += e[c]; }
        float inv = 1.0f / s;
#pragma unroll
        for (int c = 0; c < GG; c++)
            g_gates[warp * GG + c] = e[c] * inv;
    }
}

// ---------------- kernel 2: transpose lora_A -> [d][e*16+r] (R1-proven) ----------------
__global__ void transpose_A_kernel(const float* __restrict__ loraA)
{
    int total = EE * DD * RR;
    for (int i = blockIdx.x * blockDim.x + threadIdx.x; i < total;
         i += gridDim.x * blockDim.x) {
        int e = i / (DD * RR);
        int d = (i / RR) % DD;
        int r = i % RR;
        g_At[d * ER + e * RR + r] = loraA[i];
    }
}

// ---------------- kernel 3: t'[n,c] = gate[n,1+c/16] * (x@At)[n,c] (R1-proven) ----
__global__ void loraA_kernel(const float* __restrict__ x)
{
    __shared__ float xs[16][32];
    __shared__ float as[16][ER];

    int tid  = threadIdx.x;
    int tcol = tid & 31;
    int trow = tid >> 5;
    int rowBase = blockIdx.x * 32;

    float acc[4][4];
#pragma unroll
    for (int i = 0; i < 4; i++)
#pragma unroll
        for (int j = 0; j < 4; j++) acc[i][j] = 0.f;

    for (int k0 = 0; k0 < DD; k0 += 16) {
#pragma unroll
        for (int j = 0; j < 2; j++) {
            int i = tid * 2 + j;
            int row = i >> 4;
            int kk  = i & 15;
            xs[kk][row] = x[(size_t)(rowBase + row) * DD + k0 + kk];
        }
#pragma unroll
        for (int j = 0; j < 2; j++) {
            int i = tid + j * 256;
            int kk = i >> 5;
            int c4 = i & 31;
            *(float4*)&as[kk][c4 * 4] =
                *(const float4*)&g_At[(size_t)(k0 + kk) * ER + c4 * 4];
        }
        __syncthreads();
#pragma unroll
        for (int kk = 0; kk < 16; kk++) {
            float ra[4], rb[4];
            *(float4*)ra = *(const float4*)&xs[kk][trow * 4];
            *(float4*)rb = *(const float4*)&as[kk][tcol * 4];
#pragma unroll
            for (int i = 0; i < 4; i++)
#pragma unroll
                for (int j = 0; j < 4; j++)
                    acc[i][j] += ra[i] * rb[j];
        }
        __syncthreads();
    }
#pragma unroll
    for (int i = 0; i < 4; i++) {
        int row = rowBase + trow * 4 + i;
#pragma unroll
        for (int j = 0; j < 4; j++) {
            int col = tcol * 4 + j;
            float g = g_gates[row * GG + 1 + (col >> 4)];
            g_t[(size_t)row * ER + col] = g * acc[i][j];
        }
    }
}

// ---------------- kernel 4: pipelined tensor-core GEMM, in-kernel bf16 split ----------------
// acc = x@W (256 chunks of K=16), then acc *= g0, then acc += t'@B_flat (8 chunks),
// epilogue: out = acc + g0*bias.  Split-bf16 3 passes per chunk, fp32 accumulators.
// BM=BN=128, BK=16, 8 warps (2x4), warp tile 64x32, 256 threads.
// Double-buffered static smem: compute(c) overlaps LDG(c+1); convert+STS(c+1) after.
#define SA 24    // A smem stride (ushorts): conflict-free fragment loads
#define SB 132   // B smem stride (ushorts)
#define NC0 256  // chunks in base GEMM (4096/16)
#define NC  264  // + 8 lora chunks (128/16)

__global__ void __launch_bounds__(256) mma_fused_kernel(const float* __restrict__ x,
                                                        const float* __restrict__ W,
                                                        const float* __restrict__ bias,
                                                        const float* __restrict__ loraB,
                                                        float* __restrict__ out)
{
    __shared__ __align__(16) unsigned short Ah[2][128][SA];
    __shared__ __align__(16) unsigned short Al[2][128][SA];
    __shared__ __align__(16) unsigned short Bh[2][16][SB];
    __shared__ __align__(16) unsigned short Bl[2][16][SB];

    int tid  = threadIdx.x;
    int wid  = tid >> 5;
    int lane = tid & 31;
    int gid  = lane >> 2;   // 0..7
    int tig  = lane & 3;    // 0..3
    int wm = wid >> 2;      // 0..1 (m offset *64)
    int wn = wid & 3;       // 0..3 (n offset *32)
    int rowBase = blockIdx.y * 128;
    int colBase = blockIdx.x * 128;

    float acc[4][4][4];
#pragma unroll
    for (int mi = 0; mi < 4; mi++)
#pragma unroll
        for (int ni = 0; ni < 4; ni++)
#pragma unroll
            for (int q = 0; q < 4; q++) acc[mi][ni][q] = 0.f;

    // per-thread tile slots:
    // A tile (128x16 fp32 = 512 float4): rows tid>>2 and 64+(tid>>2), quad tid&3
    // B tile (16x128 fp32 = 512 float4): k-rows tid>>5 and 8+(tid>>5), quad tid&31
    int arow = tid >> 2, aq = tid & 3;
    int bkr  = tid >> 5, bq = tid & 31;

    float4 ra[2], rb[2];

    auto ldreg = [&](int c) {
        const float *Asrc, *Bsrc;
        int Kp, k0;
        if (c < NC0) { Asrc = x;   Bsrc = W;     Kp = DD; k0 = c * 16; }
        else         { Asrc = g_t; Bsrc = loraB; Kp = ER; k0 = (c - NC0) * 16; }
        ra[0] = *(const float4*)&Asrc[(size_t)(rowBase + arow) * Kp + k0 + aq * 4];
        ra[1] = *(const float4*)&Asrc[(size_t)(rowBase + arow + 64) * Kp + k0 + aq * 4];
        rb[0] = *(const float4*)&Bsrc[(size_t)(k0 + bkr) * OO + colBase + bq * 4];
        rb[1] = *(const float4*)&Bsrc[(size_t)(k0 + bkr + 8) * OO + colBase + bq * 4];
    };

    auto convst = [&](int s) {
#pragma unroll
        for (int j = 0; j < 2; j++) {
            uint32_t h0, l0, h1, l1;
            split2(ra[j].x, ra[j].y, h0, l0);
            split2(ra[j].z, ra[j].w, h1, l1);
            int row = arow + j * 64;
            *(uint2*)&Ah[s][row][aq * 4] = make_uint2(h0, h1);
            *(uint2*)&Al[s][row][aq * 4] = make_uint2(l0, l1);
            split2(rb[j].x, rb[j].y, h0, l0);
            split2(rb[j].z, rb[j].w, h1, l1);
            int kr = bkr + j * 8;
            *(uint2*)&Bh[s][kr][bq * 4] = make_uint2(h0, h1);
            *(uint2*)&Bl[s][kr][bq * 4] = make_uint2(l0, l1);
        }
    };

    auto compute = [&](int s) {
        int kb = tig * 2;
        uint32_t bhf[4][2], blf[4][2];
#pragma unroll
        for (int ni = 0; ni < 4; ni++) {
            int n = wn * 32 + ni * 8 + gid;
            bhf[ni][0] = (uint32_t)Bh[s][kb][n]     | ((uint32_t)Bh[s][kb + 1][n] << 16);
            bhf[ni][1] = (uint32_t)Bh[s][kb + 8][n] | ((uint32_t)Bh[s][kb + 9][n] << 16);
            blf[ni][0] = (uint32_t)Bl[s][kb][n]     | ((uint32_t)Bl[s][kb + 1][n] << 16);
            blf[ni][1] = (uint32_t)Bl[s][kb + 8][n] | ((uint32_t)Bl[s][kb + 9][n] << 16);
        }
#pragma unroll
        for (int mi = 0; mi < 4; mi++) {
            int r = wm * 64 + mi * 16 + gid;
            uint32_t ah[4], al[4];
            ah[0] = *(const uint32_t*)&Ah[s][r][kb];
            ah[1] = *(const uint32_t*)&Ah[s][r + 8][kb];
            ah[2] = *(const uint32_t*)&Ah[s][r][kb + 8];
            ah[3] = *(const uint32_t*)&Ah[s][r + 8][kb + 8];
            al[0] = *(const uint32_t*)&Al[s][r][kb];
            al[1] = *(const uint32_t*)&Al[s][r + 8][kb];
            al[2] = *(const uint32_t*)&Al[s][r][kb + 8];
            al[3] = *(const uint32_t*)&Al[s][r + 8][kb + 8];
#pragma unroll
            for (int ni = 0; ni < 4; ni++) {
                mma16816(acc[mi][ni], ah, bhf[ni]);
                mma16816(acc[mi][ni], ah, blf[ni]);
                mma16816(acc[mi][ni], al, bhf[ni]);
            }
        }
    };

    // prologue
    ldreg(0);
    convst(0);
    __syncthreads();

#pragma unroll 1
    for (int c = 0; c < NC; c++) {
        if (c + 1 < NC) ldreg(c + 1);       // LDGs in flight, hidden by compute
        if (c == NC0) {
            // base GEMM done: scale accumulators by base gate g0
#pragma unroll
            for (int mi = 0; mi < 4; mi++) {
                int rg = rowBase + wm * 64 + mi * 16 + gid;
                float g0a = g_gates[rg * GG];
                float g0b = g_gates[(rg + 8) * GG];
#pragma unroll
                for (int ni = 0; ni < 4; ni++) {
                    acc[mi][ni][0] *= g0a;
                    acc[mi][ni][1] *= g0a;
                    acc[mi][ni][2] *= g0b;
                    acc[mi][ni][3] *= g0b;
                }
            }
        }
        compute(c & 1);
        if (c + 1 < NC) convst((c + 1) & 1);
        __syncthreads();
    }

    // ----- epilogue: out = acc + g0 * bias -----
#pragma unroll
    for (int mi = 0; mi < 4; mi++) {
        int ra2 = rowBase + wm * 64 + mi * 16 + gid;
#pragma unroll
        for (int half = 0; half < 2; half++) {
            int row = ra2 + half * 8;
            float g0 = g_gates[row * GG];
#pragma unroll
            for (int ni = 0; ni < 4; ni++) {
                int col = colBase + wn * 32 + ni * 8 + tig * 2;
                float2 v;
                v.x = acc[mi][ni][half * 2 + 0] + g0 * bias[col];
                v.y = acc[mi][ni][half * 2 + 1] + g0 * bias[col + 1];
                *(float2*)&out[(size_t)row * OO + col] = v;
            }
        }
    }
}

// ---------------- launcher ----------------
extern "C" void kernel_launch(void* const* d_in, const int* in_sizes, int n_in,
                              void* d_out, int out_size)
{
    const float* x      = (const float*)d_in[0];
    const float* W      = (const float*)d_in[1];
    const float* bias   = (const float*)d_in[2];
    const float* loraA  = (const float*)d_in[3];
    const float* loraB  = (const float*)d_in[4];
    const float* gw     = (const float*)d_in[5];
    // d_in[6] = bvv (unused by the reference computation)
    float* out = (float*)d_out;

    gate_kernel<<<NN / 8, 256>>>(x, gw);
    transpose_A_kernel<<<512, 256>>>(loraA);
    loraA_kernel<<<NN / 32, 256>>>(x);
    mma_fused_kernel<<<dim3(OO / 128, NN / 128), 256>>>(x, W, bias, loraB, out);
}

// round 9
// speedup vs baseline: 3.0769x; 1.3413x over previous
#include <cuda_runtime.h>
#include <cuda_bf16.h>
#include <math.h>
#include <stdint.h>

// ---------------- problem constants ----------------
#define NN 4096
#define DD 4096
#define OO 4096
#define EE 8
#define RR 16
#define ER 128      // E*R
#define GG 9        // E+1

// ---------------- device scratch (small — proven safe footprint) ----------------
__device__ float g_gates[NN * GG];      // softmax gates per row (base + 8 experts)
__device__ float g_t[NN * ER];          // gated LoRA intermediate t'[n, e*16+r]
__device__ float g_At[DD * ER];         // lora_A transposed to [d][e*16+r]

// ---------------- tf32 helpers (sm_80+ baseline ISA) ----------------
__device__ __forceinline__ uint32_t to_tf32(float v) {
    uint32_t r;
    asm("cvt.rna.tf32.f32 %0, %1;" : "=r"(r) : "f"(v));
    return r;
}
__device__ __forceinline__ void mma_tf32(float* c, const uint32_t* a, const uint32_t* b) {
    asm volatile(
        "mma.sync.aligned.m16n8k8.row.col.f32.tf32.tf32.f32 "
        "{%0,%1,%2,%3}, {%4,%5,%6,%7}, {%8,%9}, {%0,%1,%2,%3};"
        : "+f"(c[0]), "+f"(c[1]), "+f"(c[2]), "+f"(c[3])
        : "r"(a[0]), "r"(a[1]), "r"(a[2]), "r"(a[3]), "r"(b[0]), "r"(b[1]));
}

// ---------------- kernel 1: gate logits + top2 + softmax (R1-proven) ----------------
__global__ void gate_kernel(const float* __restrict__ x,
                            const float* __restrict__ gw)
{
    int warp = (blockIdx.x * blockDim.x + threadIdx.x) >> 5;
    int lane = threadIdx.x & 31;
    if (warp >= NN) return;
    const float* xr = x + (size_t)warp * DD;

    float acc[GG];
#pragma unroll
    for (int c = 0; c < GG; c++) acc[c] = 0.f;

    for (int d = lane; d < DD; d += 32) {
        float xv = xr[d];
#pragma unroll
        for (int c = 0; c < GG; c++)
            acc[c] += xv * gw[c * DD + d];
    }
#pragma unroll
    for (int c = 0; c < GG; c++) {
#pragma unroll
        for (int off = 16; off > 0; off >>= 1)
            acc[c] += __shfl_xor_sync(0xFFFFFFFFu, acc[c], off);
    }

    if (lane == 0) {
        float m1 = -INFINITY, m2 = -INFINITY;
        int i1 = -1, i2 = -1;
#pragma unroll
        for (int c = 1; c < GG; c++) {
            float v = acc[c];
            if (v > m1) { m2 = m1; i2 = i1; m1 = v; i1 = c; }
            else if (v > m2) { m2 = v; i2 = c; }
        }
        float vals[GG];
        vals[0] = acc[0];
#pragma unroll
        for (int c = 1; c < GG; c++)
            vals[c] = (c == i1 || c == i2) ? acc[c] : 0.0f;

        float mx = vals[0];
#pragma unroll
        for (int c = 1; c < GG; c++) mx = fmaxf(mx, vals[c]);
        float s = 0.f;
        float e[GG];
#pragma unroll
        for (int c = 0; c < GG; c++) { e[c] = __expf(vals[c] - mx); s += e[c]; }
        float inv = 1.0f / s;
#pragma unroll
        for (int c = 0; c < GG; c++)
            g_gates[warp * GG + c] = e[c] * inv;
    }
}

// ---------------- kernel 2: transpose lora_A -> [d][e*16+r] (R1-proven) ----------------
__global__ void transpose_A_kernel(const float* __restrict__ loraA)
{
    int total = EE * DD * RR;
    for (int i = blockIdx.x * blockDim.x + threadIdx.x; i < total;
         i += gridDim.x * blockDim.x) {
        int e = i / (DD * RR);
        int d = (i / RR) % DD;
        int r = i % RR;
        g_At[d * ER + e * RR + r] = loraA[i];
    }
}

// ---------------- kernel 3: t'[n,c] = gate[n,1+c/16] * (x@At)[n,c] (R1-proven) ----
__global__ void loraA_kernel(const float* __restrict__ x)
{
    __shared__ float xs[16][32];
    __shared__ float as[16][ER];

    int tid  = threadIdx.x;
    int tcol = tid & 31;
    int trow = tid >> 5;
    int rowBase = blockIdx.x * 32;

    float acc[4][4];
#pragma unroll
    for (int i = 0; i < 4; i++)
#pragma unroll
        for (int j = 0; j < 4; j++) acc[i][j] = 0.f;

    for (int k0 = 0; k0 < DD; k0 += 16) {
#pragma unroll
        for (int j = 0; j < 2; j++) {
            int i = tid * 2 + j;
            int row = i >> 4;
            int kk  = i & 15;
            xs[kk][row] = x[(size_t)(rowBase + row) * DD + k0 + kk];
        }
#pragma unroll
        for (int j = 0; j < 2; j++) {
            int i = tid + j * 256;
            int kk = i >> 5;
            int c4 = i & 31;
            *(float4*)&as[kk][c4 * 4] =
                *(const float4*)&g_At[(size_t)(k0 + kk) * ER + c4 * 4];
        }
        __syncthreads();
#pragma unroll
        for (int kk = 0; kk < 16; kk++) {
            float ra[4], rb[4];
            *(float4*)ra = *(const float4*)&xs[kk][trow * 4];
            *(float4*)rb = *(const float4*)&as[kk][tcol * 4];
#pragma unroll
            for (int i = 0; i < 4; i++)
#pragma unroll
                for (int j = 0; j < 4; j++)
                    acc[i][j] += ra[i] * rb[j];
        }
        __syncthreads();
    }
#pragma unroll
    for (int i = 0; i < 4; i++) {
        int row = rowBase + trow * 4 + i;
#pragma unroll
        for (int j = 0; j < 4; j++) {
            int col = tcol * 4 + j;
            float g = g_gates[row * GG + 1 + (col >> 4)];
            g_t[(size_t)row * ER + col] = g * acc[i][j];
        }
    }
}

// ---------------- kernel 4: pipelined tf32 tensor-core GEMM ----------------
// acc = x@W (256 chunks of K=16), then acc *= g0, then acc += t'@B_flat (8 chunks),
// epilogue: out = acc + g0*bias.  Single-pass tf32 (cvt.rna), fp32 accumulators.
// BM=BN=128, BK=16 (2x m16n8k8 steps), 8 warps (2x4), warp tile 64x32, 256 threads.
// Double-buffered static smem; compute(c) overlaps LDG(c+1); convert+STS(c+1) after.
#define SA 20    // A smem stride in u32 (16 + pad4): frag banks 20*gid+tig all distinct
#define SB 136   // B smem stride in u32 (128 + pad8): frag banks 8*tig+gid all distinct
#define NC0 256  // chunks in base GEMM (4096/16)
#define NC  264  // + 8 lora chunks (128/16)

__global__ void __launch_bounds__(256) mma_fused_kernel(const float* __restrict__ x,
                                                        const float* __restrict__ W,
                                                        const float* __restrict__ bias,
                                                        const float* __restrict__ loraB,
                                                        float* __restrict__ out)
{
    __shared__ __align__(16) uint32_t At[2][128][SA];   // 20480 B
    __shared__ __align__(16) uint32_t Bt[2][16][SB];    // 17408 B

    int tid  = threadIdx.x;
    int wid  = tid >> 5;
    int lane = tid & 31;
    int gid  = lane >> 2;   // 0..7
    int tig  = lane & 3;    // 0..3
    int wm = wid >> 2;      // 0..1 (m offset *64)
    int wn = wid & 3;       // 0..3 (n offset *32)
    int rowBase = blockIdx.y * 128;
    int colBase = blockIdx.x * 128;

    float acc[4][4][4];
#pragma unroll
    for (int mi = 0; mi < 4; mi++)
#pragma unroll
        for (int ni = 0; ni < 4; ni++)
#pragma unroll
            for (int q = 0; q < 4; q++) acc[mi][ni][q] = 0.f;

    // per-thread tile slots:
    // A tile (128x16 fp32 = 512 float4): rows tid>>2 and 64+(tid>>2), quad tid&3
    // B tile (16x128 fp32 = 512 float4): k-rows tid>>5 and 8+(tid>>5), quad tid&31
    int arow = tid >> 2, aq = tid & 3;
    int bkr  = tid >> 5, bq = tid & 31;

    float4 ra[2], rb[2];

    auto ldreg = [&](int c) {
        const float *Asrc, *Bsrc;
        int Kp, k0;
        if (c < NC0) { Asrc = x;   Bsrc = W;     Kp = DD; k0 = c * 16; }
        else         { Asrc = g_t; Bsrc = loraB; Kp = ER; k0 = (c - NC0) * 16; }
        ra[0] = *(const float4*)&Asrc[(size_t)(rowBase + arow) * Kp + k0 + aq * 4];
        ra[1] = *(const float4*)&Asrc[(size_t)(rowBase + arow + 64) * Kp + k0 + aq * 4];
        rb[0] = *(const float4*)&Bsrc[(size_t)(k0 + bkr) * OO + colBase + bq * 4];
        rb[1] = *(const float4*)&Bsrc[(size_t)(k0 + bkr + 8) * OO + colBase + bq * 4];
    };

    auto convst = [&](int s) {
#pragma unroll
        for (int j = 0; j < 2; j++) {
            uint32_t t0 = to_tf32(ra[j].x), t1 = to_tf32(ra[j].y);
            uint32_t t2 = to_tf32(ra[j].z), t3 = to_tf32(ra[j].w);
            int row = arow + j * 64;
            *(uint2*)&At[s][row][aq * 4]     = make_uint2(t0, t1);
            *(uint2*)&At[s][row][aq * 4 + 2] = make_uint2(t2, t3);
            t0 = to_tf32(rb[j].x); t1 = to_tf32(rb[j].y);
            t2 = to_tf32(rb[j].z); t3 = to_tf32(rb[j].w);
            int kr = bkr + j * 8;
            *(uint4*)&Bt[s][kr][bq * 4] = make_uint4(t0, t1, t2, t3);
        }
    };

    auto compute = [&](int buf) {
#pragma unroll
        for (int s = 0; s < 2; s++) {
            int k0 = s * 8 + tig;
            uint32_t bf[4][2];
#pragma unroll
            for (int ni = 0; ni < 4; ni++) {
                int n = wn * 32 + ni * 8 + gid;
                bf[ni][0] = Bt[buf][k0][n];
                bf[ni][1] = Bt[buf][k0 + 4][n];
            }
#pragma unroll
            for (int mi = 0; mi < 4; mi++) {
                int r = wm * 64 + mi * 16 + gid;
                uint32_t af[4];
                af[0] = At[buf][r][k0];
                af[1] = At[buf][r + 8][k0];
                af[2] = At[buf][r][k0 + 4];
                af[3] = At[buf][r + 8][k0 + 4];
#pragma unroll
                for (int ni = 0; ni < 4; ni++)
                    mma_tf32(acc[mi][ni], af, bf[ni]);
            }
        }
    };

    // prologue
    ldreg(0);
    convst(0);
    __syncthreads();

#pragma unroll 1
    for (int c = 0; c < NC; c++) {
        if (c + 1 < NC) ldreg(c + 1);       // LDGs in flight, hidden by compute
        if (c == NC0) {
            // base GEMM done: scale accumulators by base gate g0
#pragma unroll
            for (int mi = 0; mi < 4; mi++) {
                int rg = rowBase + wm * 64 + mi * 16 + gid;
                float g0a = g_gates[rg * GG];
                float g0b = g_gates[(rg + 8) * GG];
#pragma unroll
                for (int ni = 0; ni < 4; ni++) {
                    acc[mi][ni][0] *= g0a;
                    acc[mi][ni][1] *= g0a;
                    acc[mi][ni][2] *= g0b;
                    acc[mi][ni][3] *= g0b;
                }
            }
        }
        compute(c & 1);
        if (c + 1 < NC) convst((c + 1) & 1);
        __syncthreads();
    }

    // ----- epilogue: out = acc + g0 * bias -----
#pragma unroll
    for (int mi = 0; mi < 4; mi++) {
        int ra2 = rowBase + wm * 64 + mi * 16 + gid;
#pragma unroll
        for (int half = 0; half < 2; half++) {
            int row = ra2 + half * 8;
            float g0 = g_gates[row * GG];
#pragma unroll
            for (int ni = 0; ni < 4; ni++) {
                int col = colBase + wn * 32 + ni * 8 + tig * 2;
                float2 v;
                v.x = acc[mi][ni][half * 2 + 0] + g0 * bias[col];
                v.y = acc[mi][ni][half * 2 + 1] + g0 * bias[col + 1];
                *(float2*)&out[(size_t)row * OO + col] = v;
            }
        }
    }
}

// ---------------- launcher ----------------
extern "C" void kernel_launch(void* const* d_in, const int* in_sizes, int n_in,
                              void* d_out, int out_size)
{
    const float* x      = (const float*)d_in[0];
    const float* W      = (const float*)d_in[1];
    const float* bias   = (const float*)d_in[2];
    const float* loraA  = (const float*)d_in[3];
    const float* loraB  = (const float*)d_in[4];
    const float* gw     = (const float*)d_in[5];
    // d_in[6] = bvv (unused by the reference computation)
    float* out = (float*)d_out;

    gate_kernel<<<NN / 8, 256>>>(x, gw);
    transpose_A_kernel<<<512, 256>>>(loraA);
    loraA_kernel<<<NN / 32, 256>>>(x);
    mma_fused_kernel<<<dim3(OO / 128, NN / 128), 256>>>(x, W, bias, loraB, out);
}